// round 2
// baseline (speedup 1.0000x reference)
#include <cuda_runtime.h>
#include <math.h>
#include <stdint.h>

#define N_NODES 50000
#define N_EDGES 800000
#define D 128

// ---- scratch (static __device__ arrays; no allocation) ----
__device__ float g_z[(size_t)N_NODES * D];     // fc output (reused both layers)
__device__ float g_h1[(size_t)N_NODES * D];    // layer-1 output
__device__ float g_ssrc[N_NODES];
__device__ float g_sdst[N_NODES];
__device__ int   g_deg[N_NODES];               // degree, then scatter cursor
__device__ int   g_off[N_NODES + 1];           // CSR row offsets (by dst)
__device__ int   g_csr[N_EDGES];               // src ids grouped by dst

// ---- GEMM: C[M,128] = A[M,K] @ W[128,K]^T + bias ----
// BM=64, BN=128, BK=32, 256 threads, per-thread 8x4 microtile.
__global__ __launch_bounds__(256) void gemm_bias(
    const float* __restrict__ A, const float* __restrict__ W,
    const float* __restrict__ bias, float* __restrict__ C,
    int M, int K)
{
    __shared__ __align__(16) float As[32][68];   // [k][m], padded
    __shared__ __align__(16) float Bs[32][132];  // [k][n], padded

    const int tid = threadIdx.x;
    const int tx = tid & 31;        // n-groups of 4 -> covers 128
    const int ty = tid >> 5;        // m-groups of 8 -> covers 64
    const int m0 = blockIdx.x * 64;

    float acc[8][4];
#pragma unroll
    for (int i = 0; i < 8; i++)
#pragma unroll
        for (int j = 0; j < 4; j++) acc[i][j] = 0.f;

    for (int k0 = 0; k0 < K; k0 += 32) {
#pragma unroll
        for (int l = 0; l < 2; l++) {
            int idx = tid + l * 256;
            int row = idx >> 3;
            int kc  = (idx & 7) << 2;
            float4 v = make_float4(0.f, 0.f, 0.f, 0.f);
            if (m0 + row < M)
                v = *(const float4*)(A + (size_t)(m0 + row) * K + k0 + kc);
            As[kc + 0][row] = v.x; As[kc + 1][row] = v.y;
            As[kc + 2][row] = v.z; As[kc + 3][row] = v.w;
        }
#pragma unroll
        for (int l = 0; l < 4; l++) {
            int idx = tid + l * 256;
            int n  = idx >> 3;
            int kc = (idx & 7) << 2;
            float4 v = *(const float4*)(W + (size_t)n * K + k0 + kc);
            Bs[kc + 0][n] = v.x; Bs[kc + 1][n] = v.y;
            Bs[kc + 2][n] = v.z; Bs[kc + 3][n] = v.w;
        }
        __syncthreads();

#pragma unroll
        for (int k = 0; k < 32; k++) {
            float4 a0 = *(const float4*)&As[k][ty * 8];
            float4 a1 = *(const float4*)&As[k][ty * 8 + 4];
            float4 bb = *(const float4*)&Bs[k][tx * 4];
            float a[8] = {a0.x, a0.y, a0.z, a0.w, a1.x, a1.y, a1.z, a1.w};
            float b[4] = {bb.x, bb.y, bb.z, bb.w};
#pragma unroll
            for (int i = 0; i < 8; i++)
#pragma unroll
                for (int j = 0; j < 4; j++)
                    acc[i][j] = fmaf(a[i], b[j], acc[i][j]);
        }
        __syncthreads();
    }

    float4 bv = *(const float4*)(bias + tx * 4);
#pragma unroll
    for (int i = 0; i < 8; i++) {
        int m = m0 + ty * 8 + i;
        if (m < M) {
            float4 o;
            o.x = acc[i][0] + bv.x; o.y = acc[i][1] + bv.y;
            o.z = acc[i][2] + bv.z; o.w = acc[i][3] + bv.w;
            *(float4*)(C + (size_t)m * D + tx * 4) = o;
        }
    }
}

// ---- per-node attention scalars: ssrc = z.a[:128], sdst = z.a[128:] ----
__global__ __launch_bounds__(256) void node_scalars(
    const float* __restrict__ z, const float* __restrict__ a)
{
    int warp = (blockIdx.x * blockDim.x + threadIdx.x) >> 5;
    int lane = threadIdx.x & 31;
    if (warp >= N_NODES) return;
    float4 zv = *(const float4*)(z + (size_t)warp * D + lane * 4);
    float4 as = *(const float4*)(a + lane * 4);
    float4 ad = *(const float4*)(a + D + lane * 4);
    float s1 = zv.x * as.x + zv.y * as.y + zv.z * as.z + zv.w * as.w;
    float s2 = zv.x * ad.x + zv.y * ad.y + zv.z * ad.z + zv.w * ad.w;
#pragma unroll
    for (int o = 16; o; o >>= 1) {
        s1 += __shfl_xor_sync(0xFFFFFFFFu, s1, o);
        s2 += __shfl_xor_sync(0xFFFFFFFFu, s2, o);
    }
    if (lane == 0) { g_ssrc[warp] = s1; g_sdst[warp] = s2; }
}

// ================= CSR build (by dst) =================
__global__ __launch_bounds__(256) void zero_deg()
{
    int i = blockIdx.x * blockDim.x + threadIdx.x;
    if (i < N_NODES) g_deg[i] = 0;
}

__global__ __launch_bounds__(256) void count_deg(const int* __restrict__ dst)
{
    int i = blockIdx.x * blockDim.x + threadIdx.x;
    if (i < N_EDGES) atomicAdd(&g_deg[dst[i]], 1);
}

// single-block exclusive scan; also primes g_deg as the scatter cursor
__global__ __launch_bounds__(1024) void scan_deg()
{
    const int T = 1024;
    const int C = (N_NODES + T - 1) / T;  // 49
    int t = threadIdx.x;
    int base = t * C;

    int sum = 0;
    int local[49];
#pragma unroll 1
    for (int i = 0; i < C; i++) {
        int idx = base + i;
        int v = (idx < N_NODES) ? g_deg[idx] : 0;
        local[i] = v;
        sum += v;
    }

    __shared__ int sh[T];
    sh[t] = sum;
    __syncthreads();
    for (int off = 1; off < T; off <<= 1) {
        int v = (t >= off) ? sh[t - off] : 0;
        __syncthreads();
        sh[t] += v;
        __syncthreads();
    }
    int run = sh[t] - sum;  // exclusive prefix

#pragma unroll 1
    for (int i = 0; i < C; i++) {
        int idx = base + i;
        if (idx < N_NODES) {
            g_off[idx] = run;
            g_deg[idx] = run;   // cursor for scatter
            run += local[i];
        }
    }
    if (t == T - 1) g_off[N_NODES] = run;
}

__global__ __launch_bounds__(256) void scatter_edges(
    const int* __restrict__ src, const int* __restrict__ dst)
{
    int i = blockIdx.x * blockDim.x + threadIdx.x;
    if (i >= N_EDGES) return;
    int d = dst[i];
    int pos = atomicAdd(&g_deg[d], 1);
    g_csr[pos] = src[i];
}

// ================= fused softmax + aggregate + ELU =================
// One warp per dst node; lanes cover 4 feature dims each.
__global__ __launch_bounds__(256) void gat_aggregate(
    const float* __restrict__ z, const float* __restrict__ ab,
    float* __restrict__ out)
{
    int node = (blockIdx.x * blockDim.x + threadIdx.x) >> 5;
    int lane = threadIdx.x & 31;
    if (node >= N_NODES) return;

    int r0 = g_off[node];
    int r1 = g_off[node + 1];

    if (r0 == r1) {  // isolated node: sum = 0, elu(0) = 0
        float4 zz = make_float4(0.f, 0.f, 0.f, 0.f);
        *(float4*)(out + (size_t)node * D + lane * 4) = zz;
        return;
    }

    float sd = g_sdst[node] + ab[0];

    // pass 1: segment max (lanes strided over edges)
    float m = -INFINITY;
    for (int j = r0 + lane; j < r1; j += 32) {
        float e = g_ssrc[g_csr[j]] + sd;
        e = (e > 0.f) ? e : 0.01f * e;
        m = fmaxf(m, e);
    }
#pragma unroll
    for (int o = 16; o; o >>= 1)
        m = fmaxf(m, __shfl_xor_sync(0xFFFFFFFFu, m, o));

    // pass 2: denom
    float den = 0.f;
    for (int j = r0 + lane; j < r1; j += 32) {
        float e = g_ssrc[g_csr[j]] + sd;
        e = (e > 0.f) ? e : 0.01f * e;
        den += expf(e - m);
    }
#pragma unroll
    for (int o = 16; o; o >>= 1)
        den += __shfl_xor_sync(0xFFFFFFFFu, den, o);
    float inv_den = 1.f / den;

    // pass 3: sequential edge walk, register accumulation
    float4 acc = make_float4(0.f, 0.f, 0.f, 0.f);
    for (int j = r0; j < r1; j++) {
        int s = g_csr[j];                        // broadcast load
        float e = g_ssrc[s] + sd;                // broadcast load
        e = (e > 0.f) ? e : 0.01f * e;
        float alpha = expf(e - m) * inv_den;
        float4 zv = *(const float4*)(z + (size_t)s * D + lane * 4);
        acc.x = fmaf(alpha, zv.x, acc.x);
        acc.y = fmaf(alpha, zv.y, acc.y);
        acc.z = fmaf(alpha, zv.z, acc.z);
        acc.w = fmaf(alpha, zv.w, acc.w);
    }

    // fused ELU
    acc.x = (acc.x > 0.f) ? acc.x : expm1f(acc.x);
    acc.y = (acc.y > 0.f) ? acc.y : expm1f(acc.y);
    acc.z = (acc.z > 0.f) ? acc.z : expm1f(acc.z);
    acc.w = (acc.w > 0.f) ? acc.w : expm1f(acc.w);
    *(float4*)(out + (size_t)node * D + lane * 4) = acc;
}

extern "C" void kernel_launch(void* const* d_in, const int* in_sizes, int n_in,
                              void* d_out, int out_size)
{
    const float* h   = (const float*)d_in[0];
    const int*   src = (const int*)  d_in[1];
    const int*   dst = (const int*)  d_in[2];
    const float* W1  = (const float*)d_in[3];
    const float* b1  = (const float*)d_in[4];
    const float* a1  = (const float*)d_in[5];
    const float* ab1 = (const float*)d_in[6];
    const float* W2  = (const float*)d_in[7];
    const float* b2  = (const float*)d_in[8];
    const float* a2  = (const float*)d_in[9];
    const float* ab2 = (const float*)d_in[10];
    float* out = (float*)d_out;

    float *z, *h1;
    cudaGetSymbolAddress((void**)&z,  g_z);
    cudaGetSymbolAddress((void**)&h1, g_h1);

    const int GEMM_BLOCKS  = (N_NODES + 63) / 64;   // 782
    const int NODE_BLOCKS  = (N_NODES + 255) / 256; // 196
    const int SCAL_BLOCKS  = (N_NODES + 7) / 8;     // 6250 (warp/node)
    const int EDGE_BLOCKS  = (N_EDGES + 255) / 256; // 3125
    const int AGG_BLOCKS   = (N_NODES + 7) / 8;     // 6250 (warp/node)

    // ---- CSR build (once; shared by both layers) ----
    zero_deg<<<NODE_BLOCKS, 256>>>();
    count_deg<<<EDGE_BLOCKS, 256>>>(dst);
    scan_deg<<<1, 1024>>>();
    scatter_edges<<<EDGE_BLOCKS, 256>>>(src, dst);

    // ---- layer 1 ----
    gemm_bias<<<GEMM_BLOCKS, 256>>>(h, W1, b1, z, N_NODES, 256);
    node_scalars<<<SCAL_BLOCKS, 256>>>(z, a1);
    gat_aggregate<<<AGG_BLOCKS, 256>>>(z, ab1, h1);

    // ---- layer 2 ----
    gemm_bias<<<GEMM_BLOCKS, 256>>>(h1, W2, b2, z, N_NODES, 128);
    node_scalars<<<SCAL_BLOCKS, 256>>>(z, a2);
    gat_aggregate<<<AGG_BLOCKS, 256>>>(z, ab2, out);
}

// round 3
// speedup vs baseline: 1.9374x; 1.9374x over previous
#include <cuda_runtime.h>
#include <math.h>
#include <stdint.h>

#define N_NODES 50000
#define N_EDGES 800000
#define D 128

// ---- scratch (static __device__ arrays; no allocation) ----
__device__ float g_z[(size_t)N_NODES * D];     // fc output (reused both layers)
__device__ float g_h1[(size_t)N_NODES * D];    // layer-1 output
__device__ float g_ssrc[N_NODES];
__device__ float g_sdst[N_NODES];
__device__ int   g_deg[N_NODES];               // degree
__device__ int   g_cur[N_NODES];               // scatter cursor
__device__ int   g_off[N_NODES + 1];           // CSR row offsets (by dst)
__device__ int   g_csr[N_EDGES];               // src ids grouped by dst
__device__ int   g_pos[N_EDGES];               // edge id -> csr slot
__device__ float g_w[N_EDGES];                 // per-edge exp weight, CSR order
__device__ int   g_part[256];                  // block partial sums for scan

// ---- GEMM: C[M,128] = A[M,K] @ W[128,K]^T + bias ----
__global__ __launch_bounds__(256) void gemm_bias(
    const float* __restrict__ A, const float* __restrict__ W,
    const float* __restrict__ bias, float* __restrict__ C,
    int M, int K)
{
    __shared__ __align__(16) float As[32][68];
    __shared__ __align__(16) float Bs[32][132];

    const int tid = threadIdx.x;
    const int tx = tid & 31;
    const int ty = tid >> 5;
    const int m0 = blockIdx.x * 64;

    float acc[8][4];
#pragma unroll
    for (int i = 0; i < 8; i++)
#pragma unroll
        for (int j = 0; j < 4; j++) acc[i][j] = 0.f;

    for (int k0 = 0; k0 < K; k0 += 32) {
#pragma unroll
        for (int l = 0; l < 2; l++) {
            int idx = tid + l * 256;
            int row = idx >> 3;
            int kc  = (idx & 7) << 2;
            float4 v = make_float4(0.f, 0.f, 0.f, 0.f);
            if (m0 + row < M)
                v = *(const float4*)(A + (size_t)(m0 + row) * K + k0 + kc);
            As[kc + 0][row] = v.x; As[kc + 1][row] = v.y;
            As[kc + 2][row] = v.z; As[kc + 3][row] = v.w;
        }
#pragma unroll
        for (int l = 0; l < 4; l++) {
            int idx = tid + l * 256;
            int n  = idx >> 3;
            int kc = (idx & 7) << 2;
            float4 v = *(const float4*)(W + (size_t)n * K + k0 + kc);
            Bs[kc + 0][n] = v.x; Bs[kc + 1][n] = v.y;
            Bs[kc + 2][n] = v.z; Bs[kc + 3][n] = v.w;
        }
        __syncthreads();

#pragma unroll
        for (int k = 0; k < 32; k++) {
            float4 a0 = *(const float4*)&As[k][ty * 8];
            float4 a1 = *(const float4*)&As[k][ty * 8 + 4];
            float4 bb = *(const float4*)&Bs[k][tx * 4];
            float a[8] = {a0.x, a0.y, a0.z, a0.w, a1.x, a1.y, a1.z, a1.w};
            float b[4] = {bb.x, bb.y, bb.z, bb.w};
#pragma unroll
            for (int i = 0; i < 8; i++)
#pragma unroll
                for (int j = 0; j < 4; j++)
                    acc[i][j] = fmaf(a[i], b[j], acc[i][j]);
        }
        __syncthreads();
    }

    float4 bv = *(const float4*)(bias + tx * 4);
#pragma unroll
    for (int i = 0; i < 8; i++) {
        int m = m0 + ty * 8 + i;
        if (m < M) {
            float4 o;
            o.x = acc[i][0] + bv.x; o.y = acc[i][1] + bv.y;
            o.z = acc[i][2] + bv.z; o.w = acc[i][3] + bv.w;
            *(float4*)(C + (size_t)m * D + tx * 4) = o;
        }
    }
}

// ---- per-node attention scalars ----
__global__ __launch_bounds__(256) void node_scalars(
    const float* __restrict__ z, const float* __restrict__ a)
{
    int warp = (blockIdx.x * blockDim.x + threadIdx.x) >> 5;
    int lane = threadIdx.x & 31;
    if (warp >= N_NODES) return;
    float4 zv = *(const float4*)(z + (size_t)warp * D + lane * 4);
    float4 as = *(const float4*)(a + lane * 4);
    float4 ad = *(const float4*)(a + D + lane * 4);
    float s1 = zv.x * as.x + zv.y * as.y + zv.z * as.z + zv.w * as.w;
    float s2 = zv.x * ad.x + zv.y * ad.y + zv.z * ad.z + zv.w * ad.w;
#pragma unroll
    for (int o = 16; o; o >>= 1) {
        s1 += __shfl_xor_sync(0xFFFFFFFFu, s1, o);
        s2 += __shfl_xor_sync(0xFFFFFFFFu, s2, o);
    }
    if (lane == 0) { g_ssrc[warp] = s1; g_sdst[warp] = s2; }
}

// ================= CSR build (by dst) =================
__global__ __launch_bounds__(256) void zero_deg()
{
    int i = blockIdx.x * blockDim.x + threadIdx.x;
    if (i < N_NODES) g_deg[i] = 0;
}

__global__ __launch_bounds__(256) void count_deg(const int* __restrict__ dst)
{
    int i = blockIdx.x * blockDim.x + threadIdx.x;
    if (i < N_EDGES) atomicAdd(&g_deg[dst[i]], 1);
}

// k1: per-block sums of 256 degrees -> g_part[block]
__global__ __launch_bounds__(256) void scan_blocksum()
{
    __shared__ int sh[256];
    int i = blockIdx.x * 256 + threadIdx.x;
    int v = (i < N_NODES) ? g_deg[i] : 0;
    sh[threadIdx.x] = v;
    __syncthreads();
#pragma unroll
    for (int o = 128; o; o >>= 1) {
        if (threadIdx.x < o) sh[threadIdx.x] += sh[threadIdx.x + o];
        __syncthreads();
    }
    if (threadIdx.x == 0) g_part[blockIdx.x] = sh[0];
}

// k2: exclusive scan of the block partials (single block)
__global__ __launch_bounds__(256) void scan_partials(int nblocks)
{
    __shared__ int sh[256];
    int t = threadIdx.x;
    int v = (t < nblocks) ? g_part[t] : 0;
    sh[t] = v;
    __syncthreads();
    for (int o = 1; o < 256; o <<= 1) {
        int u = (t >= o) ? sh[t - o] : 0;
        __syncthreads();
        sh[t] += u;
        __syncthreads();
    }
    if (t < nblocks) g_part[t] = sh[t] - v;   // exclusive
    if (t == 255) g_off[N_NODES] = sh[255];
}

// k3: block-level exclusive scan of degrees + block base -> g_off, g_cur
__global__ __launch_bounds__(256) void scan_writeoff()
{
    __shared__ int sh[256];
    int i = blockIdx.x * 256 + threadIdx.x;
    int t = threadIdx.x;
    int v = (i < N_NODES) ? g_deg[i] : 0;
    sh[t] = v;
    __syncthreads();
    for (int o = 1; o < 256; o <<= 1) {
        int u = (t >= o) ? sh[t - o] : 0;
        __syncthreads();
        sh[t] += u;
        __syncthreads();
    }
    if (i < N_NODES) {
        int off = g_part[blockIdx.x] + sh[t] - v;
        g_off[i] = off;
        g_cur[i] = off;
    }
}

__global__ __launch_bounds__(256) void scatter_edges(
    const int* __restrict__ src, const int* __restrict__ dst)
{
    int i = blockIdx.x * blockDim.x + threadIdx.x;
    if (i >= N_EDGES) return;
    int d = dst[i];
    int pos = atomicAdd(&g_cur[d], 1);
    g_csr[pos] = src[i];
    g_pos[i] = pos;
}

// ---- edge-parallel exp weights into CSR order ----
__global__ __launch_bounds__(256) void edge_weights(
    const int* __restrict__ src, const int* __restrict__ dst,
    const float* __restrict__ ab)
{
    int i = blockIdx.x * blockDim.x + threadIdx.x;
    if (i >= N_EDGES) return;
    float e = g_ssrc[src[i]] + g_sdst[dst[i]] + ab[0];
    e = (e > 0.f) ? e : 0.01f * e;
    g_w[g_pos[i]] = expf(e);   // |e| small by construction -> exp safe, no max needed
}

// ================= fused aggregate + normalize + ELU =================
// One warp per dst node; single pass, folded denominator.
__global__ __launch_bounds__(256) void gat_aggregate(
    const float* __restrict__ z, float* __restrict__ out)
{
    int node = (blockIdx.x * blockDim.x + threadIdx.x) >> 5;
    int lane = threadIdx.x & 31;
    if (node >= N_NODES) return;

    int r0 = g_off[node];
    int r1 = g_off[node + 1];

    if (r0 == r1) {  // isolated: sum=0, elu(0)=0
        *(float4*)(out + (size_t)node * D + lane * 4) =
            make_float4(0.f, 0.f, 0.f, 0.f);
        return;
    }

    float4 acc = make_float4(0.f, 0.f, 0.f, 0.f);
    float den = 0.f;

    for (int t = r0; t < r1; t += 32) {
        int n = min(32, r1 - t);
        int s = 0;
        float w = 0.f;
        if (lane < n) {
            s = g_csr[t + lane];   // coalesced
            w = g_w[t + lane];     // coalesced
        }
        den += w;
#pragma unroll 4
        for (int k = 0; k < n; k++) {
            int   ss = __shfl_sync(0xFFFFFFFFu, s, k);
            float ww = __shfl_sync(0xFFFFFFFFu, w, k);
            float4 zv = *(const float4*)(z + (size_t)ss * D + lane * 4);
            acc.x = fmaf(ww, zv.x, acc.x);
            acc.y = fmaf(ww, zv.y, acc.y);
            acc.z = fmaf(ww, zv.z, acc.z);
            acc.w = fmaf(ww, zv.w, acc.w);
        }
    }

#pragma unroll
    for (int o = 16; o; o >>= 1)
        den += __shfl_xor_sync(0xFFFFFFFFu, den, o);
    float inv = 1.f / den;

    acc.x *= inv; acc.y *= inv; acc.z *= inv; acc.w *= inv;
    acc.x = (acc.x > 0.f) ? acc.x : expm1f(acc.x);
    acc.y = (acc.y > 0.f) ? acc.y : expm1f(acc.y);
    acc.z = (acc.z > 0.f) ? acc.z : expm1f(acc.z);
    acc.w = (acc.w > 0.f) ? acc.w : expm1f(acc.w);
    *(float4*)(out + (size_t)node * D + lane * 4) = acc;
}

extern "C" void kernel_launch(void* const* d_in, const int* in_sizes, int n_in,
                              void* d_out, int out_size)
{
    const float* h   = (const float*)d_in[0];
    const int*   src = (const int*)  d_in[1];
    const int*   dst = (const int*)  d_in[2];
    const float* W1  = (const float*)d_in[3];
    const float* b1  = (const float*)d_in[4];
    const float* a1  = (const float*)d_in[5];
    const float* ab1 = (const float*)d_in[6];
    const float* W2  = (const float*)d_in[7];
    const float* b2  = (const float*)d_in[8];
    const float* a2  = (const float*)d_in[9];
    const float* ab2 = (const float*)d_in[10];
    float* out = (float*)d_out;

    float *z, *h1;
    cudaGetSymbolAddress((void**)&z,  g_z);
    cudaGetSymbolAddress((void**)&h1, g_h1);

    const int GEMM_BLOCKS = (N_NODES + 63) / 64;    // 782
    const int NODE_BLOCKS = (N_NODES + 255) / 256;  // 196
    const int SCAL_BLOCKS = (N_NODES + 7) / 8;      // 6250 (warp/node)
    const int EDGE_BLOCKS = (N_EDGES + 255) / 256;  // 3125
    const int AGG_BLOCKS  = (N_NODES + 7) / 8;      // 6250 (warp/node)

    // ---- CSR build (once; shared by both layers) ----
    zero_deg<<<NODE_BLOCKS, 256>>>();
    count_deg<<<EDGE_BLOCKS, 256>>>(dst);
    scan_blocksum<<<NODE_BLOCKS, 256>>>();
    scan_partials<<<1, 256>>>(NODE_BLOCKS);
    scan_writeoff<<<NODE_BLOCKS, 256>>>();
    scatter_edges<<<EDGE_BLOCKS, 256>>>(src, dst);

    // ---- layer 1 ----
    gemm_bias<<<GEMM_BLOCKS, 256>>>(h, W1, b1, z, N_NODES, 256);
    node_scalars<<<SCAL_BLOCKS, 256>>>(z, a1);
    edge_weights<<<EDGE_BLOCKS, 256>>>(src, dst, ab1);
    gat_aggregate<<<AGG_BLOCKS, 256>>>(z, h1);

    // ---- layer 2 ----
    gemm_bias<<<GEMM_BLOCKS, 256>>>(h1, W2, b2, z, N_NODES, 128);
    node_scalars<<<SCAL_BLOCKS, 256>>>(z, a2);
    edge_weights<<<EDGE_BLOCKS, 256>>>(src, dst, ab2);
    gat_aggregate<<<AGG_BLOCKS, 256>>>(z, out);
}

// round 4
// speedup vs baseline: 2.6017x; 1.3429x over previous
#include <cuda_runtime.h>
#include <cuda_bf16.h>
#include <mma.h>
#include <math.h>
#include <stdint.h>

using namespace nvcuda;

#define N_NODES 50000
#define N_EDGES 800000
#define D 128

#define BM 64
#define BN 128
#define BK 32
#define LDT 40    // bf16 smem tile leading dim (80 B, mult of 16 B)
#define LDC 132   // fp32 C tile leading dim

// ---- scratch (static __device__ arrays; no allocation) ----
__device__ float g_z[(size_t)N_NODES * D];
__device__ float g_h1[(size_t)N_NODES * D];
__device__ float g_ssrc[N_NODES];
__device__ float g_sdst[N_NODES];
__device__ int   g_deg[N_NODES];
__device__ int   g_cur[N_NODES];
__device__ int   g_off[N_NODES + 1];
__device__ int   g_csr[N_EDGES];
__device__ int   g_pos[N_EDGES];
__device__ float g_w[N_EDGES];
__device__ int   g_part[256];

__device__ __forceinline__ __nv_bfloat16 bfhi(float f) {
    return __float2bfloat16_rn(f);
}
__device__ __forceinline__ __nv_bfloat16 bflo(float f, __nv_bfloat16 hi) {
    return __float2bfloat16_rn(f - __bfloat162float(hi));
}

// ---- GEMM: z[M,128] = A[M,K] @ W[128,K]^T + bias; fused ssrc/sdst dots ----
// bf16 hi/lo split, 3-product wmma (err ~2^-16). 256 thr, 8 warps (2x4).
__global__ __launch_bounds__(256) void gemm_bias_scal(
    const float* __restrict__ A, const float* __restrict__ W,
    const float* __restrict__ bias, const float* __restrict__ avec,
    float* __restrict__ C, int M, int K)
{
    static __shared__ union {
        struct {
            __nv_bfloat16 Ahi[BM][LDT], Alo[BM][LDT];
            __nv_bfloat16 Whi[BN][LDT], Wlo[BN][LDT];
        } t;
        float Cs[BM][LDC];
    } sm;

    const int tid = threadIdx.x;
    const int m0 = blockIdx.x * BM;
    const int w  = tid >> 5;
    const int wm = w >> 2;          // 0..1 : rows [wm*32, wm*32+32)
    const int wn = w & 3;           // 0..3 : cols [wn*32, wn*32+32)

    wmma::fragment<wmma::accumulator, 16, 16, 16, float> c[2][2];
#pragma unroll
    for (int i = 0; i < 2; i++)
#pragma unroll
        for (int j = 0; j < 2; j++) wmma::fill_fragment(c[i][j], 0.f);

    for (int k0 = 0; k0 < K; k0 += BK) {
        // A tile: 64x32 floats = 512 float4; 2 per thread
#pragma unroll
        for (int l = 0; l < 2; l++) {
            int idx = tid + l * 256;
            int row = idx >> 3;
            int kc  = (idx & 7) << 2;
            float4 v = make_float4(0.f, 0.f, 0.f, 0.f);
            if (m0 + row < M)
                v = *(const float4*)(A + (size_t)(m0 + row) * K + k0 + kc);
            __nv_bfloat16 hx = bfhi(v.x), hy = bfhi(v.y), hz = bfhi(v.z), hw = bfhi(v.w);
            *(__nv_bfloat162*)&sm.t.Ahi[row][kc]     = __nv_bfloat162(hx, hy);
            *(__nv_bfloat162*)&sm.t.Ahi[row][kc + 2] = __nv_bfloat162(hz, hw);
            *(__nv_bfloat162*)&sm.t.Alo[row][kc]     = __nv_bfloat162(bflo(v.x, hx), bflo(v.y, hy));
            *(__nv_bfloat162*)&sm.t.Alo[row][kc + 2] = __nv_bfloat162(bflo(v.z, hz), bflo(v.w, hw));
        }
        // W tile: 128x32 floats = 1024 float4; 4 per thread
#pragma unroll
        for (int l = 0; l < 4; l++) {
            int idx = tid + l * 256;
            int n  = idx >> 3;
            int kc = (idx & 7) << 2;
            float4 v = *(const float4*)(W + (size_t)n * K + k0 + kc);
            __nv_bfloat16 hx = bfhi(v.x), hy = bfhi(v.y), hz = bfhi(v.z), hw = bfhi(v.w);
            *(__nv_bfloat162*)&sm.t.Whi[n][kc]     = __nv_bfloat162(hx, hy);
            *(__nv_bfloat162*)&sm.t.Whi[n][kc + 2] = __nv_bfloat162(hz, hw);
            *(__nv_bfloat162*)&sm.t.Wlo[n][kc]     = __nv_bfloat162(bflo(v.x, hx), bflo(v.y, hy));
            *(__nv_bfloat162*)&sm.t.Wlo[n][kc + 2] = __nv_bfloat162(bflo(v.z, hz), bflo(v.w, hw));
        }
        __syncthreads();

#pragma unroll
        for (int kk = 0; kk < BK; kk += 16) {
            wmma::fragment<wmma::matrix_a, 16, 16, 16, __nv_bfloat16, wmma::row_major> ahi[2], alo[2];
            wmma::fragment<wmma::matrix_b, 16, 16, 16, __nv_bfloat16, wmma::col_major> bhi[2], blo[2];
#pragma unroll
            for (int i = 0; i < 2; i++) {
                wmma::load_matrix_sync(ahi[i], &sm.t.Ahi[wm * 32 + i * 16][kk], LDT);
                wmma::load_matrix_sync(alo[i], &sm.t.Alo[wm * 32 + i * 16][kk], LDT);
            }
#pragma unroll
            for (int j = 0; j < 2; j++) {
                wmma::load_matrix_sync(bhi[j], &sm.t.Whi[wn * 32 + j * 16][kk], LDT);
                wmma::load_matrix_sync(blo[j], &sm.t.Wlo[wn * 32 + j * 16][kk], LDT);
            }
#pragma unroll
            for (int i = 0; i < 2; i++)
#pragma unroll
                for (int j = 0; j < 2; j++) {
                    wmma::mma_sync(c[i][j], ahi[i], bhi[j], c[i][j]);
                    wmma::mma_sync(c[i][j], ahi[i], blo[j], c[i][j]);
                    wmma::mma_sync(c[i][j], alo[i], bhi[j], c[i][j]);
                }
        }
        __syncthreads();
    }

    // stage C tile in smem (union reuse)
#pragma unroll
    for (int i = 0; i < 2; i++)
#pragma unroll
        for (int j = 0; j < 2; j++)
            wmma::store_matrix_sync(&sm.Cs[wm * 32 + i * 16][wn * 32 + j * 16],
                                    c[i][j], LDC, wmma::mem_row_major);
    __syncthreads();

    // epilogue: bias add, write z, fused per-row dots with avec
    const int tx = tid & 31;
    const int ty = tid >> 5;
    float4 bv  = *(const float4*)(bias + tx * 4);
    float4 a1v = *(const float4*)(avec + tx * 4);
    float4 a2v = *(const float4*)(avec + D + tx * 4);
#pragma unroll
    for (int i = 0; i < 8; i++) {
        int row = ty * 8 + i;
        int m = m0 + row;
        float4 cv = *(const float4*)&sm.Cs[row][tx * 4];
        cv.x += bv.x; cv.y += bv.y; cv.z += bv.z; cv.w += bv.w;
        if (m < M)
            *(float4*)(C + (size_t)m * D + tx * 4) = cv;
        float s1 = cv.x * a1v.x + cv.y * a1v.y + cv.z * a1v.z + cv.w * a1v.w;
        float s2 = cv.x * a2v.x + cv.y * a2v.y + cv.z * a2v.z + cv.w * a2v.w;
#pragma unroll
        for (int o = 16; o; o >>= 1) {
            s1 += __shfl_xor_sync(0xFFFFFFFFu, s1, o);
            s2 += __shfl_xor_sync(0xFFFFFFFFu, s2, o);
        }
        if (tx == 0 && m < M) { g_ssrc[m] = s1; g_sdst[m] = s2; }
    }
}

// ================= CSR build (by dst) =================
__global__ __launch_bounds__(256) void zero_deg()
{
    int i = blockIdx.x * blockDim.x + threadIdx.x;
    if (i < N_NODES) g_deg[i] = 0;
}

__global__ __launch_bounds__(256) void count_deg(const int* __restrict__ dst)
{
    int i = blockIdx.x * blockDim.x + threadIdx.x;
    if (i < N_EDGES) atomicAdd(&g_deg[dst[i]], 1);
}

__global__ __launch_bounds__(256) void scan_blocksum()
{
    __shared__ int sh[256];
    int i = blockIdx.x * 256 + threadIdx.x;
    int v = (i < N_NODES) ? g_deg[i] : 0;
    sh[threadIdx.x] = v;
    __syncthreads();
#pragma unroll
    for (int o = 128; o; o >>= 1) {
        if (threadIdx.x < o) sh[threadIdx.x] += sh[threadIdx.x + o];
        __syncthreads();
    }
    if (threadIdx.x == 0) g_part[blockIdx.x] = sh[0];
}

__global__ __launch_bounds__(256) void scan_partials(int nblocks)
{
    __shared__ int sh[256];
    int t = threadIdx.x;
    int v = (t < nblocks) ? g_part[t] : 0;
    sh[t] = v;
    __syncthreads();
    for (int o = 1; o < 256; o <<= 1) {
        int u = (t >= o) ? sh[t - o] : 0;
        __syncthreads();
        sh[t] += u;
        __syncthreads();
    }
    if (t < nblocks) g_part[t] = sh[t] - v;
    if (t == 255) g_off[N_NODES] = sh[255];
}

__global__ __launch_bounds__(256) void scan_writeoff()
{
    __shared__ int sh[256];
    int i = blockIdx.x * 256 + threadIdx.x;
    int t = threadIdx.x;
    int v = (i < N_NODES) ? g_deg[i] : 0;
    sh[t] = v;
    __syncthreads();
    for (int o = 1; o < 256; o <<= 1) {
        int u = (t >= o) ? sh[t - o] : 0;
        __syncthreads();
        sh[t] += u;
        __syncthreads();
    }
    if (i < N_NODES) {
        int off = g_part[blockIdx.x] + sh[t] - v;
        g_off[i] = off;
        g_cur[i] = off;
    }
}

__global__ __launch_bounds__(256) void scatter_edges(
    const int* __restrict__ src, const int* __restrict__ dst)
{
    int i = blockIdx.x * blockDim.x + threadIdx.x;
    if (i >= N_EDGES) return;
    int d = dst[i];
    int pos = atomicAdd(&g_cur[d], 1);
    g_csr[pos] = src[i];
    g_pos[i] = pos;
}

// ---- edge-parallel exp weights into CSR order ----
__global__ __launch_bounds__(256) void edge_weights(
    const int* __restrict__ src, const int* __restrict__ dst,
    const float* __restrict__ ab)
{
    int i = blockIdx.x * blockDim.x + threadIdx.x;
    if (i >= N_EDGES) return;
    float e = g_ssrc[src[i]] + g_sdst[dst[i]] + ab[0];
    e = (e > 0.f) ? e : 0.01f * e;
    g_w[g_pos[i]] = expf(e);
}

// ================= fused aggregate + normalize + ELU =================
__global__ __launch_bounds__(256) void gat_aggregate(
    const float* __restrict__ z, float* __restrict__ out)
{
    int node = (blockIdx.x * blockDim.x + threadIdx.x) >> 5;
    int lane = threadIdx.x & 31;
    if (node >= N_NODES) return;

    int r0 = g_off[node];
    int r1 = g_off[node + 1];

    if (r0 == r1) {
        *(float4*)(out + (size_t)node * D + lane * 4) =
            make_float4(0.f, 0.f, 0.f, 0.f);
        return;
    }

    float4 acc = make_float4(0.f, 0.f, 0.f, 0.f);
    float den = 0.f;

    for (int t = r0; t < r1; t += 32) {
        int n = min(32, r1 - t);
        int s = 0;
        float wv = 0.f;
        if (lane < n) {
            s  = g_csr[t + lane];
            wv = g_w[t + lane];
        }
        den += wv;
#pragma unroll 4
        for (int k = 0; k < n; k++) {
            int   ss = __shfl_sync(0xFFFFFFFFu, s, k);
            float ww = __shfl_sync(0xFFFFFFFFu, wv, k);
            float4 zv = *(const float4*)(z + (size_t)ss * D + lane * 4);
            acc.x = fmaf(ww, zv.x, acc.x);
            acc.y = fmaf(ww, zv.y, acc.y);
            acc.z = fmaf(ww, zv.z, acc.z);
            acc.w = fmaf(ww, zv.w, acc.w);
        }
    }

#pragma unroll
    for (int o = 16; o; o >>= 1)
        den += __shfl_xor_sync(0xFFFFFFFFu, den, o);
    float inv = 1.f / den;

    acc.x *= inv; acc.y *= inv; acc.z *= inv; acc.w *= inv;
    acc.x = (acc.x > 0.f) ? acc.x : expm1f(acc.x);
    acc.y = (acc.y > 0.f) ? acc.y : expm1f(acc.y);
    acc.z = (acc.z > 0.f) ? acc.z : expm1f(acc.z);
    acc.w = (acc.w > 0.f) ? acc.w : expm1f(acc.w);
    *(float4*)(out + (size_t)node * D + lane * 4) = acc;
}

extern "C" void kernel_launch(void* const* d_in, const int* in_sizes, int n_in,
                              void* d_out, int out_size)
{
    const float* h   = (const float*)d_in[0];
    const int*   src = (const int*)  d_in[1];
    const int*   dst = (const int*)  d_in[2];
    const float* W1  = (const float*)d_in[3];
    const float* b1  = (const float*)d_in[4];
    const float* a1  = (const float*)d_in[5];
    const float* ab1 = (const float*)d_in[6];
    const float* W2  = (const float*)d_in[7];
    const float* b2  = (const float*)d_in[8];
    const float* a2  = (const float*)d_in[9];
    const float* ab2 = (const float*)d_in[10];
    float* out = (float*)d_out;

    float *z, *h1;
    cudaGetSymbolAddress((void**)&z,  g_z);
    cudaGetSymbolAddress((void**)&h1, g_h1);

    const int GEMM_BLOCKS = (N_NODES + BM - 1) / BM; // 782
    const int NODE_BLOCKS = (N_NODES + 255) / 256;   // 196
    const int EDGE_BLOCKS = (N_EDGES + 255) / 256;   // 3125
    const int AGG_BLOCKS  = (N_NODES + 7) / 8;       // 6250 (warp/node)

    // ---- CSR build (once; shared by both layers) ----
    zero_deg<<<NODE_BLOCKS, 256>>>();
    count_deg<<<EDGE_BLOCKS, 256>>>(dst);
    scan_blocksum<<<NODE_BLOCKS, 256>>>();
    scan_partials<<<1, 256>>>(NODE_BLOCKS);
    scan_writeoff<<<NODE_BLOCKS, 256>>>();
    scatter_edges<<<EDGE_BLOCKS, 256>>>(src, dst);

    // ---- layer 1 ----
    gemm_bias_scal<<<GEMM_BLOCKS, 256>>>(h, W1, b1, a1, z, N_NODES, 256);
    edge_weights<<<EDGE_BLOCKS, 256>>>(src, dst, ab1);
    gat_aggregate<<<AGG_BLOCKS, 256>>>(z, h1);

    // ---- layer 2 ----
    gemm_bias_scal<<<GEMM_BLOCKS, 256>>>(h1, W2, b2, a2, z, N_NODES, 128);
    edge_weights<<<EDGE_BLOCKS, 256>>>(src, dst, ab2);
    gat_aggregate<<<AGG_BLOCKS, 256>>>(z, out);
}

// round 5
// speedup vs baseline: 3.0205x; 1.1610x over previous
#include <cuda_runtime.h>
#include <cuda_bf16.h>
#include <mma.h>
#include <math.h>
#include <stdint.h>

using namespace nvcuda;

#define N_NODES 50000
#define N_EDGES 800000
#define D 128

#define BM 64
#define BN 128
#define BK 32
#define LDT 40    // bf16 smem tile leading dim
#define LDC 132   // fp32 C tile leading dim

// ---- scratch (static __device__ arrays; zero-initialized at load) ----
__device__ float g_z[(size_t)N_NODES * D];
__device__ float g_h1[(size_t)N_NODES * D];
__device__ float g_ssrc[N_NODES];
__device__ float g_sdst[N_NODES];
__device__ int   g_deg[N_NODES];     // zero at entry (static init / end-of-launch re-zero)
__device__ int   g_cur[N_NODES];
__device__ int   g_off[N_NODES + 1];
__device__ int   g_csr[N_EDGES];
__device__ int   g_part[256];

__device__ __forceinline__ __nv_bfloat16 bfhi(float f) {
    return __float2bfloat16_rn(f);
}
__device__ __forceinline__ __nv_bfloat16 bflo(float f, __nv_bfloat16 hi) {
    return __float2bfloat16_rn(f - __bfloat162float(hi));
}

// ---- GEMM: z[M,128] = A[M,K] @ W[128,K]^T + bias; fused ssrc/sdst dots ----
__global__ __launch_bounds__(256) void gemm_bias_scal(
    const float* __restrict__ A, const float* __restrict__ W,
    const float* __restrict__ bias, const float* __restrict__ avec,
    float* __restrict__ C, int M, int K)
{
    static __shared__ union {
        struct {
            __nv_bfloat16 Ahi[BM][LDT], Alo[BM][LDT];
            __nv_bfloat16 Whi[BN][LDT], Wlo[BN][LDT];
        } t;
        float Cs[BM][LDC];
    } sm;

    const int tid = threadIdx.x;
    const int m0 = blockIdx.x * BM;
    const int w  = tid >> 5;
    const int wm = w >> 2;
    const int wn = w & 3;

    wmma::fragment<wmma::accumulator, 16, 16, 16, float> c[2][2];
#pragma unroll
    for (int i = 0; i < 2; i++)
#pragma unroll
        for (int j = 0; j < 2; j++) wmma::fill_fragment(c[i][j], 0.f);

    for (int k0 = 0; k0 < K; k0 += BK) {
#pragma unroll
        for (int l = 0; l < 2; l++) {
            int idx = tid + l * 256;
            int row = idx >> 3;
            int kc  = (idx & 7) << 2;
            float4 v = make_float4(0.f, 0.f, 0.f, 0.f);
            if (m0 + row < M)
                v = *(const float4*)(A + (size_t)(m0 + row) * K + k0 + kc);
            __nv_bfloat16 hx = bfhi(v.x), hy = bfhi(v.y), hz = bfhi(v.z), hw = bfhi(v.w);
            *(__nv_bfloat162*)&sm.t.Ahi[row][kc]     = __nv_bfloat162(hx, hy);
            *(__nv_bfloat162*)&sm.t.Ahi[row][kc + 2] = __nv_bfloat162(hz, hw);
            *(__nv_bfloat162*)&sm.t.Alo[row][kc]     = __nv_bfloat162(bflo(v.x, hx), bflo(v.y, hy));
            *(__nv_bfloat162*)&sm.t.Alo[row][kc + 2] = __nv_bfloat162(bflo(v.z, hz), bflo(v.w, hw));
        }
#pragma unroll
        for (int l = 0; l < 4; l++) {
            int idx = tid + l * 256;
            int n  = idx >> 3;
            int kc = (idx & 7) << 2;
            float4 v = *(const float4*)(W + (size_t)n * K + k0 + kc);
            __nv_bfloat16 hx = bfhi(v.x), hy = bfhi(v.y), hz = bfhi(v.z), hw = bfhi(v.w);
            *(__nv_bfloat162*)&sm.t.Whi[n][kc]     = __nv_bfloat162(hx, hy);
            *(__nv_bfloat162*)&sm.t.Whi[n][kc + 2] = __nv_bfloat162(hz, hw);
            *(__nv_bfloat162*)&sm.t.Wlo[n][kc]     = __nv_bfloat162(bflo(v.x, hx), bflo(v.y, hy));
            *(__nv_bfloat162*)&sm.t.Wlo[n][kc + 2] = __nv_bfloat162(bflo(v.z, hz), bflo(v.w, hw));
        }
        __syncthreads();

#pragma unroll
        for (int kk = 0; kk < BK; kk += 16) {
            wmma::fragment<wmma::matrix_a, 16, 16, 16, __nv_bfloat16, wmma::row_major> ahi[2], alo[2];
            wmma::fragment<wmma::matrix_b, 16, 16, 16, __nv_bfloat16, wmma::col_major> bhi[2], blo[2];
#pragma unroll
            for (int i = 0; i < 2; i++) {
                wmma::load_matrix_sync(ahi[i], &sm.t.Ahi[wm * 32 + i * 16][kk], LDT);
                wmma::load_matrix_sync(alo[i], &sm.t.Alo[wm * 32 + i * 16][kk], LDT);
            }
#pragma unroll
            for (int j = 0; j < 2; j++) {
                wmma::load_matrix_sync(bhi[j], &sm.t.Whi[wn * 32 + j * 16][kk], LDT);
                wmma::load_matrix_sync(blo[j], &sm.t.Wlo[wn * 32 + j * 16][kk], LDT);
            }
#pragma unroll
            for (int i = 0; i < 2; i++)
#pragma unroll
                for (int j = 0; j < 2; j++) {
                    wmma::mma_sync(c[i][j], ahi[i], bhi[j], c[i][j]);
                    wmma::mma_sync(c[i][j], ahi[i], blo[j], c[i][j]);
                    wmma::mma_sync(c[i][j], alo[i], bhi[j], c[i][j]);
                }
        }
        __syncthreads();
    }

#pragma unroll
    for (int i = 0; i < 2; i++)
#pragma unroll
        for (int j = 0; j < 2; j++)
            wmma::store_matrix_sync(&sm.Cs[wm * 32 + i * 16][wn * 32 + j * 16],
                                    c[i][j], LDC, wmma::mem_row_major);
    __syncthreads();

    const int tx = tid & 31;
    const int ty = tid >> 5;
    float4 bv  = *(const float4*)(bias + tx * 4);
    float4 a1v = *(const float4*)(avec + tx * 4);
    float4 a2v = *(const float4*)(avec + D + tx * 4);
#pragma unroll
    for (int i = 0; i < 8; i++) {
        int row = ty * 8 + i;
        int m = m0 + row;
        float4 cv = *(const float4*)&sm.Cs[row][tx * 4];
        cv.x += bv.x; cv.y += bv.y; cv.z += bv.z; cv.w += bv.w;
        if (m < M)
            *(float4*)(C + (size_t)m * D + tx * 4) = cv;
        float s1 = cv.x * a1v.x + cv.y * a1v.y + cv.z * a1v.z + cv.w * a1v.w;
        float s2 = cv.x * a2v.x + cv.y * a2v.y + cv.z * a2v.z + cv.w * a2v.w;
#pragma unroll
        for (int o = 16; o; o >>= 1) {
            s1 += __shfl_xor_sync(0xFFFFFFFFu, s1, o);
            s2 += __shfl_xor_sync(0xFFFFFFFFu, s2, o);
        }
        if (tx == 0 && m < M) { g_ssrc[m] = s1; g_sdst[m] = s2; }
    }
}

// ================= CSR build (by dst) =================
__global__ __launch_bounds__(256) void zero_deg()
{
    int i = blockIdx.x * blockDim.x + threadIdx.x;
    if (i < N_NODES) g_deg[i] = 0;
}

__global__ __launch_bounds__(256) void count_deg(const int* __restrict__ dst)
{
    int i = blockIdx.x * blockDim.x + threadIdx.x;
    if (i < N_EDGES) atomicAdd(&g_deg[dst[i]], 1);
}

__global__ __launch_bounds__(256) void scan_blocksum()
{
    __shared__ int sh[256];
    int i = blockIdx.x * 256 + threadIdx.x;
    int v = (i < N_NODES) ? g_deg[i] : 0;
    sh[threadIdx.x] = v;
    __syncthreads();
#pragma unroll
    for (int o = 128; o; o >>= 1) {
        if (threadIdx.x < o) sh[threadIdx.x] += sh[threadIdx.x + o];
        __syncthreads();
    }
    if (threadIdx.x == 0) g_part[blockIdx.x] = sh[0];
}

__global__ __launch_bounds__(256) void scan_partials(int nblocks)
{
    __shared__ int sh[256];
    int t = threadIdx.x;
    int v = (t < nblocks) ? g_part[t] : 0;
    sh[t] = v;
    __syncthreads();
    for (int o = 1; o < 256; o <<= 1) {
        int u = (t >= o) ? sh[t - o] : 0;
        __syncthreads();
        sh[t] += u;
        __syncthreads();
    }
    if (t < nblocks) g_part[t] = sh[t] - v;
    if (t == 255) g_off[N_NODES] = sh[255];
}

__global__ __launch_bounds__(256) void scan_writeoff()
{
    __shared__ int sh[256];
    int i = blockIdx.x * 256 + threadIdx.x;
    int t = threadIdx.x;
    int v = (i < N_NODES) ? g_deg[i] : 0;
    sh[t] = v;
    __syncthreads();
    for (int o = 1; o < 256; o <<= 1) {
        int u = (t >= o) ? sh[t - o] : 0;
        __syncthreads();
        sh[t] += u;
        __syncthreads();
    }
    if (i < N_NODES) {
        int off = g_part[blockIdx.x] + sh[t] - v;
        g_off[i] = off;
        g_cur[i] = off;
    }
}

__global__ __launch_bounds__(256) void scatter_edges(
    const int* __restrict__ src, const int* __restrict__ dst)
{
    int i = blockIdx.x * blockDim.x + threadIdx.x;
    if (i >= N_EDGES) return;
    int d = dst[i];
    int pos = atomicAdd(&g_cur[d], 1);
    g_csr[pos] = src[i];
}

// ======= fused exp + aggregate + normalize + ELU (one warp / node) =======
__global__ __launch_bounds__(256) void gat_aggregate(
    const float* __restrict__ z, const float* __restrict__ ab,
    float* __restrict__ out)
{
    int node = (blockIdx.x * blockDim.x + threadIdx.x) >> 5;
    int lane = threadIdx.x & 31;
    if (node >= N_NODES) return;

    int r0 = g_off[node];
    int r1 = g_off[node + 1];

    if (r0 == r1) {
        *(float4*)(out + (size_t)node * D + lane * 4) =
            make_float4(0.f, 0.f, 0.f, 0.f);
        return;
    }

    float sd = g_sdst[node] + ab[0];
    float4 acc = make_float4(0.f, 0.f, 0.f, 0.f);
    float den = 0.f;

    for (int t = r0; t < r1; t += 32) {
        int n = min(32, r1 - t);
        int s = 0;
        float wv = 0.f;
        if (lane < n) {
            s = g_csr[t + lane];            // coalesced
            float e = g_ssrc[s] + sd;       // 4B gather (L2)
            e = (e > 0.f) ? e : 0.01f * e;
            wv = expf(e);                   // folded-denominator weight
        }
        den += wv;
#pragma unroll 4
        for (int k = 0; k < n; k++) {
            int   ss = __shfl_sync(0xFFFFFFFFu, s, k);
            float ww = __shfl_sync(0xFFFFFFFFu, wv, k);
            float4 zv = *(const float4*)(z + (size_t)ss * D + lane * 4);
            acc.x = fmaf(ww, zv.x, acc.x);
            acc.y = fmaf(ww, zv.y, acc.y);
            acc.z = fmaf(ww, zv.z, acc.z);
            acc.w = fmaf(ww, zv.w, acc.w);
        }
    }

#pragma unroll
    for (int o = 16; o; o >>= 1)
        den += __shfl_xor_sync(0xFFFFFFFFu, den, o);
    float inv = 1.f / den;

    acc.x *= inv; acc.y *= inv; acc.z *= inv; acc.w *= inv;
    acc.x = (acc.x > 0.f) ? acc.x : expm1f(acc.x);
    acc.y = (acc.y > 0.f) ? acc.y : expm1f(acc.y);
    acc.z = (acc.z > 0.f) ? acc.z : expm1f(acc.z);
    acc.w = (acc.w > 0.f) ? acc.w : expm1f(acc.w);
    *(float4*)(out + (size_t)node * D + lane * 4) = acc;
}

extern "C" void kernel_launch(void* const* d_in, const int* in_sizes, int n_in,
                              void* d_out, int out_size)
{
    const float* h   = (const float*)d_in[0];
    const int*   src = (const int*)  d_in[1];
    const int*   dst = (const int*)  d_in[2];
    const float* W1  = (const float*)d_in[3];
    const float* b1  = (const float*)d_in[4];
    const float* a1  = (const float*)d_in[5];
    const float* ab1 = (const float*)d_in[6];
    const float* W2  = (const float*)d_in[7];
    const float* b2  = (const float*)d_in[8];
    const float* a2  = (const float*)d_in[9];
    const float* ab2 = (const float*)d_in[10];
    float* out = (float*)d_out;

    float *z, *h1;
    cudaGetSymbolAddress((void**)&z,  g_z);
    cudaGetSymbolAddress((void**)&h1, g_h1);

    // lazily-created side stream + fork/join events (no device memory involved)
    static cudaStream_t s2 = nullptr;
    static cudaEvent_t ev_fork = nullptr, ev_join = nullptr;
    if (s2 == nullptr) {
        cudaStreamCreateWithFlags(&s2, cudaStreamNonBlocking);
        cudaEventCreateWithFlags(&ev_fork, cudaEventDisableTiming);
        cudaEventCreateWithFlags(&ev_join, cudaEventDisableTiming);
    }

    const int GEMM_BLOCKS = (N_NODES + BM - 1) / BM; // 782
    const int NODE_BLOCKS = (N_NODES + 255) / 256;   // 196
    const int EDGE_BLOCKS = (N_EDGES + 255) / 256;   // 3125
    const int AGG_BLOCKS  = (N_NODES + 7) / 8;       // 6250

    // ---- fork: CSR build on side stream (g_deg is zero at entry) ----
    cudaEventRecord(ev_fork, 0);
    cudaStreamWaitEvent(s2, ev_fork, 0);
    count_deg<<<EDGE_BLOCKS, 256, 0, s2>>>(dst);
    scan_blocksum<<<NODE_BLOCKS, 256, 0, s2>>>();
    scan_partials<<<1, 256, 0, s2>>>(NODE_BLOCKS);
    scan_writeoff<<<NODE_BLOCKS, 256, 0, s2>>>();
    scatter_edges<<<EDGE_BLOCKS, 256, 0, s2>>>(src, dst);
    cudaEventRecord(ev_join, s2);

    // ---- main stream: GEMM1 runs concurrently with the CSR build ----
    gemm_bias_scal<<<GEMM_BLOCKS, 256>>>(h, W1, b1, a1, z, N_NODES, 256);
    cudaStreamWaitEvent(0, ev_join, 0);   // join before aggregate needs CSR

    gat_aggregate<<<AGG_BLOCKS, 256>>>(z, ab1, h1);

    gemm_bias_scal<<<GEMM_BLOCKS, 256>>>(h1, W2, b2, a2, z, N_NODES, 128);
    gat_aggregate<<<AGG_BLOCKS, 256>>>(z, ab2, out);

    // re-zero g_deg for the next invocation (keeps zero-at-entry invariant)
    zero_deg<<<NODE_BLOCKS, 256>>>();
}

// round 13
// speedup vs baseline: 3.1743x; 1.0509x over previous
#include <cuda_runtime.h>
#include <cuda_bf16.h>
#include <cuda_fp16.h>
#include <mma.h>
#include <math.h>
#include <stdint.h>

using namespace nvcuda;

#define N_NODES 50000
#define N_EDGES 800000
#define D 128

#define BM 64
#define BN 128
#define BK 32
#define LDT 40    // bf16 smem tile leading dim
#define LDC 132   // fp32 C tile leading dim

// ---- scratch (static __device__ arrays; zero-initialized at load) ----
__device__ __half g_zh[(size_t)N_NODES * D];   // z in fp16 (aggregate input)
__device__ float g_h1[(size_t)N_NODES * D];
__device__ float g_ssrc[N_NODES];
__device__ float g_sdst[N_NODES];
__device__ int   g_deg[N_NODES];     // zero at entry (static init / overlapped re-zero)
__device__ int   g_cur[N_NODES];
__device__ int   g_off[N_NODES + 1];
__device__ int   g_csr[N_EDGES];
__device__ int   g_part[256];

__device__ __forceinline__ __nv_bfloat16 bfhi(float f) {
    return __float2bfloat16_rn(f);
}
__device__ __forceinline__ __nv_bfloat16 bflo(float f, __nv_bfloat16 hi) {
    return __float2bfloat16_rn(f - __bfloat162float(hi));
}

// ---- GEMM: z[M,128] = A[M,K] @ W[128,K]^T + bias; z out in fp16; fused dots ----
__global__ __launch_bounds__(256) void gemm_bias_scal(
    const float* __restrict__ A, const float* __restrict__ W,
    const float* __restrict__ bias, const float* __restrict__ avec,
    __half* __restrict__ Ch, int M, int K)
{
    static __shared__ union {
        struct {
            __nv_bfloat16 Ahi[BM][LDT], Alo[BM][LDT];
            __nv_bfloat16 Whi[BN][LDT], Wlo[BN][LDT];
        } t;
        float Cs[BM][LDC];
    } sm;

    const int tid = threadIdx.x;
    const int m0 = blockIdx.x * BM;
    const int w  = tid >> 5;
    const int wm = w >> 2;
    const int wn = w & 3;

    wmma::fragment<wmma::accumulator, 16, 16, 16, float> c[2][2];
#pragma unroll
    for (int i = 0; i < 2; i++)
#pragma unroll
        for (int j = 0; j < 2; j++) wmma::fill_fragment(c[i][j], 0.f);

    for (int k0 = 0; k0 < K; k0 += BK) {
#pragma unroll
        for (int l = 0; l < 2; l++) {
            int idx = tid + l * 256;
            int row = idx >> 3;
            int kc  = (idx & 7) << 2;
            float4 v = make_float4(0.f, 0.f, 0.f, 0.f);
            if (m0 + row < M)
                v = *(const float4*)(A + (size_t)(m0 + row) * K + k0 + kc);
            __nv_bfloat16 hx = bfhi(v.x), hy = bfhi(v.y), hz = bfhi(v.z), hw = bfhi(v.w);
            *(__nv_bfloat162*)&sm.t.Ahi[row][kc]     = __nv_bfloat162(hx, hy);
            *(__nv_bfloat162*)&sm.t.Ahi[row][kc + 2] = __nv_bfloat162(hz, hw);
            *(__nv_bfloat162*)&sm.t.Alo[row][kc]     = __nv_bfloat162(bflo(v.x, hx), bflo(v.y, hy));
            *(__nv_bfloat162*)&sm.t.Alo[row][kc + 2] = __nv_bfloat162(bflo(v.z, hz), bflo(v.w, hw));
        }
#pragma unroll
        for (int l = 0; l < 4; l++) {
            int idx = tid + l * 256;
            int n  = idx >> 3;
            int kc = (idx & 7) << 2;
            float4 v = *(const float4*)(W + (size_t)n * K + k0 + kc);
            __nv_bfloat16 hx = bfhi(v.x), hy = bfhi(v.y), hz = bfhi(v.z), hw = bfhi(v.w);
            *(__nv_bfloat162*)&sm.t.Whi[n][kc]     = __nv_bfloat162(hx, hy);
            *(__nv_bfloat162*)&sm.t.Whi[n][kc + 2] = __nv_bfloat162(hz, hw);
            *(__nv_bfloat162*)&sm.t.Wlo[n][kc]     = __nv_bfloat162(bflo(v.x, hx), bflo(v.y, hy));
            *(__nv_bfloat162*)&sm.t.Wlo[n][kc + 2] = __nv_bfloat162(bflo(v.z, hz), bflo(v.w, hw));
        }
        __syncthreads();

#pragma unroll
        for (int kk = 0; kk < BK; kk += 16) {
            wmma::fragment<wmma::matrix_a, 16, 16, 16, __nv_bfloat16, wmma::row_major> ahi[2], alo[2];
            wmma::fragment<wmma::matrix_b, 16, 16, 16, __nv_bfloat16, wmma::col_major> bhi[2], blo[2];
#pragma unroll
            for (int i = 0; i < 2; i++) {
                wmma::load_matrix_sync(ahi[i], &sm.t.Ahi[wm * 32 + i * 16][kk], LDT);
                wmma::load_matrix_sync(alo[i], &sm.t.Alo[wm * 32 + i * 16][kk], LDT);
            }
#pragma unroll
            for (int j = 0; j < 2; j++) {
                wmma::load_matrix_sync(bhi[j], &sm.t.Whi[wn * 32 + j * 16][kk], LDT);
                wmma::load_matrix_sync(blo[j], &sm.t.Wlo[wn * 32 + j * 16][kk], LDT);
            }
#pragma unroll
            for (int i = 0; i < 2; i++)
#pragma unroll
                for (int j = 0; j < 2; j++) {
                    wmma::mma_sync(c[i][j], ahi[i], bhi[j], c[i][j]);
                    wmma::mma_sync(c[i][j], ahi[i], blo[j], c[i][j]);
                    wmma::mma_sync(c[i][j], alo[i], bhi[j], c[i][j]);
                }
        }
        __syncthreads();
    }

#pragma unroll
    for (int i = 0; i < 2; i++)
#pragma unroll
        for (int j = 0; j < 2; j++)
            wmma::store_matrix_sync(&sm.Cs[wm * 32 + i * 16][wn * 32 + j * 16],
                                    c[i][j], LDC, wmma::mem_row_major);
    __syncthreads();

    const int tx = tid & 31;
    const int ty = tid >> 5;
    float4 bv  = *(const float4*)(bias + tx * 4);
    float4 a1v = *(const float4*)(avec + tx * 4);
    float4 a2v = *(const float4*)(avec + D + tx * 4);
#pragma unroll
    for (int i = 0; i < 8; i++) {
        int row = ty * 8 + i;
        int m = m0 + row;
        float4 cv = *(const float4*)&sm.Cs[row][tx * 4];
        cv.x += bv.x; cv.y += bv.y; cv.z += bv.z; cv.w += bv.w;
        if (m < M) {
            __half2 p0 = __floats2half2_rn(cv.x, cv.y);
            __half2 p1 = __floats2half2_rn(cv.z, cv.w);
            uint2 pk;
            pk.x = *(unsigned*)&p0;
            pk.y = *(unsigned*)&p1;
            *(uint2*)(Ch + (size_t)m * D + tx * 4) = pk;
        }
        // scalars from full-precision accumulators
        float s1 = cv.x * a1v.x + cv.y * a1v.y + cv.z * a1v.z + cv.w * a1v.w;
        float s2 = cv.x * a2v.x + cv.y * a2v.y + cv.z * a2v.z + cv.w * a2v.w;
#pragma unroll
        for (int o = 16; o; o >>= 1) {
            s1 += __shfl_xor_sync(0xFFFFFFFFu, s1, o);
            s2 += __shfl_xor_sync(0xFFFFFFFFu, s2, o);
        }
        if (tx == 0 && m < M) { g_ssrc[m] = s1; g_sdst[m] = s2; }
    }
}

// ================= CSR build (by dst) =================
__global__ __launch_bounds__(256) void zero_deg()
{
    int i = blockIdx.x * blockDim.x + threadIdx.x;
    if (i < N_NODES) g_deg[i] = 0;
}

// 4 edges per thread (N_EDGES % 4 == 0)
__global__ __launch_bounds__(256) void count_deg(const int4* __restrict__ dst4)
{
    int i = blockIdx.x * blockDim.x + threadIdx.x;
    if (i >= N_EDGES / 4) return;
    int4 d = dst4[i];
    atomicAdd(&g_deg[d.x], 1);
    atomicAdd(&g_deg[d.y], 1);
    atomicAdd(&g_deg[d.z], 1);
    atomicAdd(&g_deg[d.w], 1);
}

__global__ __launch_bounds__(256) void scan_blocksum()
{
    __shared__ int sh[256];
    int i = blockIdx.x * 256 + threadIdx.x;
    int v = (i < N_NODES) ? g_deg[i] : 0;
    sh[threadIdx.x] = v;
    __syncthreads();
#pragma unroll
    for (int o = 128; o; o >>= 1) {
        if (threadIdx.x < o) sh[threadIdx.x] += sh[threadIdx.x + o];
        __syncthreads();
    }
    if (threadIdx.x == 0) g_part[blockIdx.x] = sh[0];
}

__global__ __launch_bounds__(256) void scan_partials(int nblocks)
{
    __shared__ int sh[256];
    int t = threadIdx.x;
    int v = (t < nblocks) ? g_part[t] : 0;
    sh[t] = v;
    __syncthreads();
    for (int o = 1; o < 256; o <<= 1) {
        int u = (t >= o) ? sh[t - o] : 0;
        __syncthreads();
        sh[t] += u;
        __syncthreads();
    }
    if (t < nblocks) g_part[t] = sh[t] - v;
    if (t == 255) g_off[N_NODES] = sh[255];
}

__global__ __launch_bounds__(256) void scan_writeoff()
{
    __shared__ int sh[256];
    int i = blockIdx.x * 256 + threadIdx.x;
    int t = threadIdx.x;
    int v = (i < N_NODES) ? g_deg[i] : 0;
    sh[t] = v;
    __syncthreads();
    for (int o = 1; o < 256; o <<= 1) {
        int u = (t >= o) ? sh[t - o] : 0;
        __syncthreads();
        sh[t] += u;
        __syncthreads();
    }
    if (i < N_NODES) {
        int off = g_part[blockIdx.x] + sh[t] - v;
        g_off[i] = off;
        g_cur[i] = off;
    }
}

// 4 edges per thread
__global__ __launch_bounds__(256) void scatter_edges(
    const int4* __restrict__ src4, const int4* __restrict__ dst4)
{
    int i = blockIdx.x * blockDim.x + threadIdx.x;
    if (i >= N_EDGES / 4) return;
    int4 s = src4[i];
    int4 d = dst4[i];
    g_csr[atomicAdd(&g_cur[d.x], 1)] = s.x;
    g_csr[atomicAdd(&g_cur[d.y], 1)] = s.y;
    g_csr[atomicAdd(&g_cur[d.z], 1)] = s.z;
    g_csr[atomicAdd(&g_cur[d.w], 1)] = s.w;
}

// ======= fused exp + aggregate + normalize + ELU (one warp / node) =======
__global__ __launch_bounds__(256) void gat_aggregate(
    const float* __restrict__ ab, float* __restrict__ out)
{
    int node = (blockIdx.x * blockDim.x + threadIdx.x) >> 5;
    int lane = threadIdx.x & 31;
    if (node >= N_NODES) return;

    int r0 = g_off[node];
    int r1 = g_off[node + 1];

    if (r0 == r1) {
        *(float4*)(out + (size_t)node * D + lane * 4) =
            make_float4(0.f, 0.f, 0.f, 0.f);
        return;
    }

    float sd = g_sdst[node] + ab[0];
    float4 acc = make_float4(0.f, 0.f, 0.f, 0.f);
    float den = 0.f;

    for (int t = r0; t < r1; t += 32) {
        int n = min(32, r1 - t);
        int s = 0;
        float wv = 0.f;
        if (lane < n) {
            s = g_csr[t + lane];            // coalesced
            float e = g_ssrc[s] + sd;       // 4B gather (L2)
            e = (e > 0.f) ? e : 0.01f * e;
            wv = expf(e);                   // folded-denominator weight
        }
        den += wv;
#pragma unroll 4
        for (int k = 0; k < n; k++) {
            int   ss = __shfl_sync(0xFFFFFFFFu, s, k);
            float ww = __shfl_sync(0xFFFFFFFFu, wv, k);
            uint2 pk = *(const uint2*)(g_zh + (size_t)ss * D + lane * 4);  // 8B/lane
            __half2 p0 = *(__half2*)&pk.x;
            __half2 p1 = *(__half2*)&pk.y;
            float2 f0 = __half22float2(p0);
            float2 f1 = __half22float2(p1);
            acc.x = fmaf(ww, f0.x, acc.x);
            acc.y = fmaf(ww, f0.y, acc.y);
            acc.z = fmaf(ww, f1.x, acc.z);
            acc.w = fmaf(ww, f1.y, acc.w);
        }
    }

#pragma unroll
    for (int o = 16; o; o >>= 1)
        den += __shfl_xor_sync(0xFFFFFFFFu, den, o);
    float inv = 1.f / den;

    acc.x *= inv; acc.y *= inv; acc.z *= inv; acc.w *= inv;
    acc.x = (acc.x > 0.f) ? acc.x : expm1f(acc.x);
    acc.y = (acc.y > 0.f) ? acc.y : expm1f(acc.y);
    acc.z = (acc.z > 0.f) ? acc.z : expm1f(acc.z);
    acc.w = (acc.w > 0.f) ? acc.w : expm1f(acc.w);
    *(float4*)(out + (size_t)node * D + lane * 4) = acc;
}

extern "C" void kernel_launch(void* const* d_in, const int* in_sizes, int n_in,
                              void* d_out, int out_size)
{
    const float* h   = (const float*)d_in[0];
    const int*   src = (const int*)  d_in[1];
    const int*   dst = (const int*)  d_in[2];
    const float* W1  = (const float*)d_in[3];
    const float* b1  = (const float*)d_in[4];
    const float* a1  = (const float*)d_in[5];
    const float* ab1 = (const float*)d_in[6];
    const float* W2  = (const float*)d_in[7];
    const float* b2  = (const float*)d_in[8];
    const float* a2  = (const float*)d_in[9];
    const float* ab2 = (const float*)d_in[10];
    float* out = (float*)d_out;

    __half* zh;
    float* h1;
    cudaGetSymbolAddress((void**)&zh, g_zh);
    cudaGetSymbolAddress((void**)&h1, g_h1);

    static cudaStream_t s2 = nullptr;
    static cudaEvent_t ev_fork = nullptr, ev_join = nullptr, ev_zero = nullptr;
    if (s2 == nullptr) {
        cudaStreamCreateWithFlags(&s2, cudaStreamNonBlocking);
        cudaEventCreateWithFlags(&ev_fork, cudaEventDisableTiming);
        cudaEventCreateWithFlags(&ev_join, cudaEventDisableTiming);
        cudaEventCreateWithFlags(&ev_zero, cudaEventDisableTiming);
    }

    const int GEMM_BLOCKS  = (N_NODES + BM - 1) / BM;    // 782
    const int NODE_BLOCKS  = (N_NODES + 255) / 256;      // 196
    const int EDGE4_BLOCKS = (N_EDGES / 4 + 255) / 256;  // 782
    const int AGG_BLOCKS   = (N_NODES + 7) / 8;          // 6250

    // ---- fork: CSR build on side stream (g_deg is zero at entry) ----
    cudaEventRecord(ev_fork, 0);
    cudaStreamWaitEvent(s2, ev_fork, 0);
    count_deg<<<EDGE4_BLOCKS, 256, 0, s2>>>((const int4*)dst);
    scan_blocksum<<<NODE_BLOCKS, 256, 0, s2>>>();
    scan_partials<<<1, 256, 0, s2>>>(NODE_BLOCKS);
    scan_writeoff<<<NODE_BLOCKS, 256, 0, s2>>>();
    scatter_edges<<<EDGE4_BLOCKS, 256, 0, s2>>>((const int4*)src, (const int4*)dst);
    cudaEventRecord(ev_join, s2);
    // overlapped re-zero for next invocation (g_deg dead after scan_writeoff);
    // ev_zero joins it back into the capture stream below.
    zero_deg<<<NODE_BLOCKS, 256, 0, s2>>>();
    cudaEventRecord(ev_zero, s2);

    // ---- main stream: GEMM1 concurrent with CSR build ----
    gemm_bias_scal<<<GEMM_BLOCKS, 256>>>(h, W1, b1, a1, zh, N_NODES, 256);
    cudaStreamWaitEvent(0, ev_join, 0);   // CSR ready

    gat_aggregate<<<AGG_BLOCKS, 256>>>(ab1, h1);

    cudaStreamWaitEvent(0, ev_zero, 0);   // rejoin ALL side-stream work
    gemm_bias_scal<<<GEMM_BLOCKS, 256>>>(h1, W2, b2, a2, zh, N_NODES, 128);
    gat_aggregate<<<AGG_BLOCKS, 256>>>(ab2, out);
}